// round 9
// baseline (speedup 1.0000x reference)
#include <cuda_runtime.h>
#include <cuda_fp16.h>
#include <cuda_bf16.h>
#include <cstdint>

#define N_NODES 50000
#define N_EDGES 800000
#define DIMS 128

#define BLOCKS 100
#define THREADS 1024
#define WARPS_TOTAL (BLOCKS * 32)
#define NODE_GROUPS (N_NODES / 4)                       // 12500 groups of 4
#define PAIRS_PER_BLOCK (N_EDGES / 2 / BLOCKS)          // 4000
#define PAIRS_PER_THREAD 4                              // 4*1024 >= 4000
#define TABLE_BYTES (N_NODES * 4)                       // half2/node = 200000 B
#define IDX_LINES_PER_BLOCK (PAIRS_PER_BLOCK * 8 / 128) // 250

// Packed per-node projections: .x = h[n]·W_src, .y = h[n]·W_dst + b.
__device__ __half2 g_ptab[N_NODES];
// Monotonic grid-barrier counter (never reset; correct across graph replays).
__device__ unsigned g_bar;

__device__ __forceinline__ uint32_t smem_u32(const void* p) {
    uint32_t a;
    asm("{ .reg .u64 t; cvta.to.shared.u64 t, %1; cvt.u32.u64 %0, t; }"
        : "=r"(a) : "l"(p));
    return a;
}

__global__ void __launch_bounds__(THREADS, 1)
fused_kernel(const float* __restrict__ h,
             const int* __restrict__ src,
             const int* __restrict__ dst,
             const float* __restrict__ W,
             const float* __restrict__ b,
             float* __restrict__ out) {
    extern __shared__ __half2 s_tab[];        // [N_NODES], 200000 B
    __shared__ __align__(8) uint64_t s_mbar;

    int tid  = threadIdx.x;
    int wid  = tid >> 5;
    int lane = tid & 31;
    uint32_t mbar = smem_u32(&s_mbar);
    uint32_t tab  = smem_u32(s_tab);

    if (tid == 0) {
        asm volatile("mbarrier.init.shared.b64 [%0], %1;"
                     :: "r"(mbar), "r"(1) : "memory");
    }

    // Warm L2 with this block's index slice (no registers held).
    int pair0 = blockIdx.x * PAIRS_PER_BLOCK;
    if (tid < IDX_LINES_PER_BLOCK) {
        const char* sb = reinterpret_cast<const char*>(src + 2 * pair0) + tid * 128;
        const char* db = reinterpret_cast<const char*>(dst + 2 * pair0) + tid * 128;
        asm volatile("prefetch.global.L2 [%0];" :: "l"(sb));
        asm volatile("prefetch.global.L2 [%0];" :: "l"(db));
    }

    // ---- Phase A: projections (warp per 4 nodes, grid-strided) ----
    {
        const float4* ws = reinterpret_cast<const float4*>(W);        // W[0:128]
        const float4* wd = reinterpret_cast<const float4*>(W + DIMS); // W[128:256]
        float4 wsv = ws[lane];
        float4 wdv = wd[lane];
        float bb = b[0];

        for (int g = blockIdx.x * 32 + wid; g < NODE_GROUPS; g += WARPS_TOTAL) {
            int n0 = g * 4;
            float4 hv[4];
            #pragma unroll
            for (int k = 0; k < 4; k++)
                hv[k] = reinterpret_cast<const float4*>(h + (size_t)(n0 + k) * DIMS)[lane];

            float s[4], d[4];
            #pragma unroll
            for (int k = 0; k < 4; k++) {
                s[k] = hv[k].x * wsv.x + hv[k].y * wsv.y + hv[k].z * wsv.z + hv[k].w * wsv.w;
                d[k] = hv[k].x * wdv.x + hv[k].y * wdv.y + hv[k].z * wdv.z + hv[k].w * wdv.w;
            }
            #pragma unroll
            for (int o = 16; o > 0; o >>= 1) {
                #pragma unroll
                for (int k = 0; k < 4; k++) {
                    s[k] += __shfl_xor_sync(0xffffffffu, s[k], o);
                    d[k] += __shfl_xor_sync(0xffffffffu, d[k], o);
                }
            }
            if (lane == 0) {
                #pragma unroll
                for (int k = 0; k < 4; k++)
                    g_ptab[n0 + k] = __floats2half2_rn(s[k], d[k] + bb);
            }
        }
    }

    // Load this thread's edge indices now — overlaps other blocks' proj tails.
    int2 sp[PAIRS_PER_THREAD], dp[PAIRS_PER_THREAD];
    #pragma unroll
    for (int k = 0; k < PAIRS_PER_THREAD; k++) {
        int r = tid + k * THREADS;
        bool v = r < PAIRS_PER_BLOCK;
        int i = pair0 + r;
        sp[k] = v ? __ldcs(reinterpret_cast<const int2*>(src) + i) : make_int2(0, 0);
        dp[k] = v ? __ldcs(reinterpret_cast<const int2*>(dst) + i) : make_int2(0, 0);
    }

    __syncthreads();

    // ---- Grid barrier (monotonic counter, replay-safe), then table DMA ----
    if (tid == 0) {
        __threadfence();  // publish this block's g_ptab writes
        unsigned my = atomicAdd(&g_bar, 1u);
        unsigned target = (my / BLOCKS) * BLOCKS + BLOCKS;
        while (*((volatile unsigned*)&g_bar) < target) { }

        asm volatile("mbarrier.arrive.expect_tx.shared.b64 _, [%0], %1;"
                     :: "r"(mbar), "r"((uint32_t)TABLE_BYTES) : "memory");
        asm volatile(
            "cp.async.bulk.shared::cta.global.mbarrier::complete_tx::bytes "
            "[%0], [%1], %2, [%3];"
            :: "r"(tab), "l"((const void*)g_ptab),
               "r"((uint32_t)TABLE_BYTES), "r"(mbar) : "memory");
    }
    __syncthreads();

    // Wait for the table DMA.
    {
        uint32_t done;
        asm volatile(
            "{\n\t.reg .pred p;\n\t"
            "mbarrier.try_wait.parity.shared.b64 p, [%1], %2;\n\t"
            "selp.b32 %0, 1, 0, p;\n\t}"
            : "=r"(done) : "r"(mbar), "r"(0u) : "memory");
        while (!done) {
            asm volatile(
                "{\n\t.reg .pred p;\n\t"
                "mbarrier.try_wait.parity.shared.b64 p, [%1], %2, 0x989680;\n\t"
                "selp.b32 %0, 1, 0, p;\n\t}"
                : "=r"(done) : "r"(mbar), "r"(0u) : "memory");
        }
    }

    // ---- Phase B: pure smem gather + store ----
    #pragma unroll
    for (int k = 0; k < PAIRS_PER_THREAD; k++) {
        int r = tid + k * THREADS;
        if (r < PAIRS_PER_BLOCK) {
            int i = pair0 + r;
            float2 o;
            o.x = __low2float(s_tab[sp[k].x]) + __high2float(s_tab[dp[k].x]);
            o.y = __low2float(s_tab[sp[k].y]) + __high2float(s_tab[dp[k].y]);
            __stcs(reinterpret_cast<float2*>(out) + i, o);
        }
    }
}

extern "C" void kernel_launch(void* const* d_in, const int* in_sizes, int n_in,
                              void* d_out, int out_size) {
    const float* h   = (const float*)d_in[0];
    const int*   src = (const int*)d_in[1];
    const int*   dst = (const int*)d_in[2];
    const float* W   = (const float*)d_in[3];
    const float* b   = (const float*)d_in[4];
    float* out = (float*)d_out;

    // Allow 200 KB dynamic smem (idempotent host-side attribute set).
    cudaFuncSetAttribute(fused_kernel,
                         cudaFuncAttributeMaxDynamicSharedMemorySize,
                         TABLE_BYTES);

    // One persistent launch: 100 blocks (all co-resident at 1 block/SM),
    // proj -> grid barrier -> table DMA -> smem gather.
    fused_kernel<<<BLOCKS, THREADS, TABLE_BYTES>>>(h, src, dst, W, b, out);
}

// round 10
// speedup vs baseline: 1.0485x; 1.0485x over previous
#include <cuda_runtime.h>
#include <cuda_fp16.h>
#include <cuda_bf16.h>
#include <cstdint>

#define N_NODES 50000
#define N_EDGES 800000
#define DIMS 128

#define NODES_PER_WARP 8
#define PROJ_WARPS (N_NODES / NODES_PER_WARP)           // 6250, exact
#define PROJ_BLOCK_WARPS 8

#define GATHER_BLOCKS 80
#define GATHER_THREADS 1024
#define PAIRS_PER_BLOCK (N_EDGES / 2 / GATHER_BLOCKS)   // 5000
#define PAIRS_PER_THREAD 5                              // 5*1024 >= 5000
#define TABLE_BYTES (N_NODES * 4)                       // half2/node = 200000 B

// Packed per-node projections: .x = h[n]·W_src, .y = h[n]·W_dst + b.
__device__ __half2 g_ptab[N_NODES];

__device__ __forceinline__ uint32_t smem_u32(const void* p) {
    uint32_t a;
    asm("{ .reg .u64 t; cvta.to.shared.u64 t, %1; cvt.u32.u64 %0, t; }"
        : "=r"(a) : "l"(p));
    return a;
}

// Kernel 1: one warp handles EIGHT nodes (MLP_p1=8 front-batched 512-B row
// loads -> saturates DRAM at 50% occupancy). Interleaved shfl tree.
__global__ void __launch_bounds__(PROJ_BLOCK_WARPS * 32)
proj_kernel(const float* __restrict__ h,
            const float* __restrict__ W,
            const float* __restrict__ b) {
    int gwarp = (blockIdx.x * blockDim.x + threadIdx.x) >> 5;
    int lane  = threadIdx.x & 31;
    if (gwarp >= PROJ_WARPS) return;
    int n0 = gwarp * NODES_PER_WARP;

    const float4* ws = reinterpret_cast<const float4*>(W);          // W[0:128]
    const float4* wd = reinterpret_cast<const float4*>(W + DIMS);   // W[128:256]
    float4 wsv = ws[lane];
    float4 wdv = wd[lane];

    float4 hv[NODES_PER_WARP];
    #pragma unroll
    for (int k = 0; k < NODES_PER_WARP; k++)
        hv[k] = reinterpret_cast<const float4*>(h + (size_t)(n0 + k) * DIMS)[lane];

    float s[NODES_PER_WARP], d[NODES_PER_WARP];
    #pragma unroll
    for (int k = 0; k < NODES_PER_WARP; k++) {
        s[k] = hv[k].x * wsv.x + hv[k].y * wsv.y + hv[k].z * wsv.z + hv[k].w * wsv.w;
        d[k] = hv[k].x * wdv.x + hv[k].y * wdv.y + hv[k].z * wdv.z + hv[k].w * wdv.w;
    }

    #pragma unroll
    for (int o = 16; o > 0; o >>= 1) {
        #pragma unroll
        for (int k = 0; k < NODES_PER_WARP; k++) {
            s[k] += __shfl_xor_sync(0xffffffffu, s[k], o);
            d[k] += __shfl_xor_sync(0xffffffffu, d[k], o);
        }
    }

    if (lane == 0) {
        float bb = b[0];
        #pragma unroll
        for (int k = 0; k < NODES_PER_WARP; k++)
            g_ptab[n0 + k] = __floats2half2_rn(s[k], d[k] + bb);
    }
}

// Kernel 2 (PDL secondary): prologue (mbarrier init + index register loads)
// overlaps proj's tail; cudaGridDependencySynchronize() gates only the table
// DMA + smem gather on proj completion.
__global__ void __launch_bounds__(GATHER_THREADS, 1)
gather_kernel(const int* __restrict__ src,
              const int* __restrict__ dst,
              float* __restrict__ out) {
    extern __shared__ __half2 s_tab[];        // [N_NODES], 200000 B
    __shared__ __align__(8) uint64_t s_mbar;

    int tid = threadIdx.x;
    uint32_t mbar = smem_u32(&s_mbar);
    uint32_t tab  = smem_u32(s_tab);

    if (tid == 0) {
        asm volatile("mbarrier.init.shared.b64 [%0], %1;"
                     :: "r"(mbar), "r"(1) : "memory");
    }

    // Prefetch indices into registers — overlaps the proj kernel via PDL.
    int pair0 = blockIdx.x * PAIRS_PER_BLOCK;
    int2 sp[PAIRS_PER_THREAD], dp[PAIRS_PER_THREAD];
    #pragma unroll
    for (int k = 0; k < PAIRS_PER_THREAD; k++) {
        int r = tid + k * GATHER_THREADS;
        bool v = r < PAIRS_PER_BLOCK;
        int i = pair0 + r;
        sp[k] = v ? __ldcs(reinterpret_cast<const int2*>(src) + i) : make_int2(0, 0);
        dp[k] = v ? __ldcs(reinterpret_cast<const int2*>(dst) + i) : make_int2(0, 0);
    }

    // Wait for proj's global writes (no-op if launched without PDL).
    cudaGridDependencySynchronize();
    __syncthreads();

    if (tid == 0) {
        asm volatile("mbarrier.arrive.expect_tx.shared.b64 _, [%0], %1;"
                     :: "r"(mbar), "r"((uint32_t)TABLE_BYTES) : "memory");
        asm volatile(
            "cp.async.bulk.shared::cta.global.mbarrier::complete_tx::bytes "
            "[%0], [%1], %2, [%3];"
            :: "r"(tab), "l"((const void*)g_ptab),
               "r"((uint32_t)TABLE_BYTES), "r"(mbar) : "memory");
    }

    // Wait for the table DMA.
    {
        uint32_t done;
        asm volatile(
            "{\n\t.reg .pred p;\n\t"
            "mbarrier.try_wait.parity.shared.b64 p, [%1], %2;\n\t"
            "selp.b32 %0, 1, 0, p;\n\t}"
            : "=r"(done) : "r"(mbar), "r"(0u) : "memory");
        while (!done) {
            asm volatile(
                "{\n\t.reg .pred p;\n\t"
                "mbarrier.try_wait.parity.shared.b64 p, [%1], %2, 0x989680;\n\t"
                "selp.b32 %0, 1, 0, p;\n\t}"
                : "=r"(done) : "r"(mbar), "r"(0u) : "memory");
        }
    }

    // Pure smem gather + store.
    #pragma unroll
    for (int k = 0; k < PAIRS_PER_THREAD; k++) {
        int r = tid + k * GATHER_THREADS;
        if (r < PAIRS_PER_BLOCK) {
            int i = pair0 + r;
            float2 o;
            o.x = __low2float(s_tab[sp[k].x]) + __high2float(s_tab[dp[k].x]);
            o.y = __low2float(s_tab[sp[k].y]) + __high2float(s_tab[dp[k].y]);
            __stcs(reinterpret_cast<float2*>(out) + i, o);
        }
    }
}

extern "C" void kernel_launch(void* const* d_in, const int* in_sizes, int n_in,
                              void* d_out, int out_size) {
    const float* h   = (const float*)d_in[0];
    const int*   src = (const int*)d_in[1];
    const int*   dst = (const int*)d_in[2];
    const float* W   = (const float*)d_in[3];
    const float* b   = (const float*)d_in[4];
    float* out = (float*)d_out;

    // Allow 200 KB dynamic smem (idempotent host-side attribute set).
    cudaFuncSetAttribute(gather_kernel,
                         cudaFuncAttributeMaxDynamicSharedMemorySize,
                         TABLE_BYTES);

    // Projection: 6250 warps (8 nodes each), 8 warps per block.
    {
        int blocks = (PROJ_WARPS + PROJ_BLOCK_WARPS - 1) / PROJ_BLOCK_WARPS;
        proj_kernel<<<blocks, PROJ_BLOCK_WARPS * 32>>>(h, W, b);
    }

    // Gather: PDL launch so its prologue overlaps proj's tail.
    {
        cudaLaunchConfig_t cfg = {};
        cfg.gridDim  = dim3(GATHER_BLOCKS, 1, 1);
        cfg.blockDim = dim3(GATHER_THREADS, 1, 1);
        cfg.dynamicSmemBytes = TABLE_BYTES;
        cfg.stream = 0;
        cudaLaunchAttribute attrs[1];
        attrs[0].id = cudaLaunchAttributeProgrammaticStreamSerialization;
        attrs[0].val.programmaticStreamSerializationAllowed = 1;
        cfg.attrs = attrs;
        cfg.numAttrs = 1;
        cudaError_t e = cudaLaunchKernelEx(&cfg, gather_kernel, src, dst, out);
        if (e != cudaSuccess) {
            // Fallback: plain launch (gridDepSync is then a no-op; stream
            // ordering provides the dependency).
            gather_kernel<<<GATHER_BLOCKS, GATHER_THREADS, TABLE_BYTES>>>(src, dst, out);
        }
    }
}

// round 12
// speedup vs baseline: 1.2237x; 1.1671x over previous
#include <cuda_runtime.h>
#include <cuda_fp16.h>
#include <cuda_bf16.h>
#include <cstdint>

#define N_NODES 50000
#define N_EDGES 800000
#define DIMS 128

#define NODES_PER_WARP 8
#define PROJ_WARPS (N_NODES / NODES_PER_WARP)           // 6250, exact
#define PROJ_BLOCK_WARPS 8

#define GATHER_BLOCKS 125
#define GATHER_THREADS 1024
#define PAIRS_PER_BLOCK 3200                            // 125*3200 = 400000 exact
#define CHUNK_PAIRS 800                                 // 4 chunks per block
#define NUM_CHUNKS (PAIRS_PER_BLOCK / CHUNK_PAIRS)      // 4
#define CHUNK_BYTES (CHUNK_PAIRS * 8)                   // 6400 B per array
#define STAGE_BYTES (2 * CHUNK_BYTES)                   // src+dst = 12800 B
#define TABLE_BYTES (N_NODES * 4)                       // 200000 B
#define SMEM_BYTES (TABLE_BYTES + 2 * STAGE_BYTES)      // 225600 B

// Packed per-node projections: .x = h[n]·W_src, .y = h[n]·W_dst + b.
__device__ __half2 g_ptab[N_NODES];

__device__ __forceinline__ uint32_t smem_u32(const void* p) {
    uint32_t a;
    asm("{ .reg .u64 t; cvta.to.shared.u64 t, %1; cvt.u32.u64 %0, t; }"
        : "=r"(a) : "l"(p));
    return a;
}

__device__ __forceinline__ void bulk_copy(uint32_t smem_dst, const void* gsrc,
                                          uint32_t bytes, uint32_t mbar) {
    asm volatile(
        "cp.async.bulk.shared::cta.global.mbarrier::complete_tx::bytes "
        "[%0], [%1], %2, [%3];"
        :: "r"(smem_dst), "l"(gsrc), "r"(bytes), "r"(mbar) : "memory");
}

__device__ __forceinline__ void mbar_wait(uint32_t mbar, uint32_t parity) {
    uint32_t done;
    asm volatile(
        "{\n\t.reg .pred p;\n\t"
        "mbarrier.try_wait.parity.shared.b64 p, [%1], %2;\n\t"
        "selp.b32 %0, 1, 0, p;\n\t}"
        : "=r"(done) : "r"(mbar), "r"(parity) : "memory");
    while (!done) {
        asm volatile(
            "{\n\t.reg .pred p;\n\t"
            "mbarrier.try_wait.parity.shared.b64 p, [%1], %2, 0x989680;\n\t"
            "selp.b32 %0, 1, 0, p;\n\t}"
            : "=r"(done) : "r"(mbar), "r"(parity) : "memory");
    }
}

// Kernel 1: one warp handles EIGHT nodes (MLP_p1=8 front-batched 512-B row
// loads). Interleaved shfl tree reduces all 16 dots.
__global__ void __launch_bounds__(PROJ_BLOCK_WARPS * 32)
proj_kernel(const float* __restrict__ h,
            const float* __restrict__ W,
            const float* __restrict__ b) {
    int gwarp = (blockIdx.x * blockDim.x + threadIdx.x) >> 5;
    int lane  = threadIdx.x & 31;
    if (gwarp >= PROJ_WARPS) return;
    int n0 = gwarp * NODES_PER_WARP;

    const float4* ws = reinterpret_cast<const float4*>(W);          // W[0:128]
    const float4* wd = reinterpret_cast<const float4*>(W + DIMS);   // W[128:256]
    float4 wsv = ws[lane];
    float4 wdv = wd[lane];

    float4 hv[NODES_PER_WARP];
    #pragma unroll
    for (int k = 0; k < NODES_PER_WARP; k++)
        hv[k] = reinterpret_cast<const float4*>(h + (size_t)(n0 + k) * DIMS)[lane];

    float s[NODES_PER_WARP], d[NODES_PER_WARP];
    #pragma unroll
    for (int k = 0; k < NODES_PER_WARP; k++) {
        s[k] = hv[k].x * wsv.x + hv[k].y * wsv.y + hv[k].z * wsv.z + hv[k].w * wsv.w;
        d[k] = hv[k].x * wdv.x + hv[k].y * wdv.y + hv[k].z * wdv.z + hv[k].w * wdv.w;
    }

    #pragma unroll
    for (int o = 16; o > 0; o >>= 1) {
        #pragma unroll
        for (int k = 0; k < NODES_PER_WARP; k++) {
            s[k] += __shfl_xor_sync(0xffffffffu, s[k], o);
            d[k] += __shfl_xor_sync(0xffffffffu, d[k], o);
        }
    }

    if (lane == 0) {
        float bb = b[0];
        #pragma unroll
        for (int k = 0; k < NODES_PER_WARP; k++)
            g_ptab[n0 + k] = __floats2half2_rn(s[k], d[k] + bb);
    }
}

// Kernel 2: indices AND table both delivered by cp.async.bulk (no register
// MLP cap). Double-buffered index chunks pipeline against the smem gather.
__global__ void __launch_bounds__(GATHER_THREADS, 1)
gather_kernel(const int* __restrict__ src,
              const int* __restrict__ dst,
              float* __restrict__ out) {
    extern __shared__ char smem_raw[];
    __half2* s_tab = reinterpret_cast<__half2*>(smem_raw);
    // Stage s: src chunk then dst chunk.
    char* stage_base = smem_raw + TABLE_BYTES;
    __shared__ __align__(8) uint64_t s_mb_tab;
    __shared__ __align__(8) uint64_t s_mb_chunk[2];

    int tid = threadIdx.x;
    uint32_t mb_tab = smem_u32(&s_mb_tab);
    uint32_t mb_ck[2] = { smem_u32(&s_mb_chunk[0]), smem_u32(&s_mb_chunk[1]) };
    uint32_t tab_addr = smem_u32(smem_raw);
    uint32_t stage_addr = smem_u32(stage_base);

    if (tid == 0) {
        asm volatile("mbarrier.init.shared.b64 [%0], %1;" :: "r"(mb_tab), "r"(1) : "memory");
        asm volatile("mbarrier.init.shared.b64 [%0], %1;" :: "r"(mb_ck[0]), "r"(1) : "memory");
        asm volatile("mbarrier.init.shared.b64 [%0], %1;" :: "r"(mb_ck[1]), "r"(1) : "memory");
    }
    __syncthreads();

    int pair0 = blockIdx.x * PAIRS_PER_BLOCK;

    // Chunk 0 index DMA can start before proj finishes (inputs only).
    if (tid == 0) {
        asm volatile("mbarrier.arrive.expect_tx.shared.b64 _, [%0], %1;"
                     :: "r"(mb_ck[0]), "r"((uint32_t)STAGE_BYTES) : "memory");
        bulk_copy(stage_addr, src + 2 * pair0, CHUNK_BYTES, mb_ck[0]);
        bulk_copy(stage_addr + CHUNK_BYTES, dst + 2 * pair0, CHUNK_BYTES, mb_ck[0]);
    }

    // Table depends on proj's writes.
    cudaGridDependencySynchronize();
    if (tid == 0) {
        asm volatile("mbarrier.arrive.expect_tx.shared.b64 _, [%0], %1;"
                     :: "r"(mb_tab), "r"((uint32_t)TABLE_BYTES) : "memory");
        bulk_copy(tab_addr, (const void*)g_ptab, TABLE_BYTES, mb_tab);
    }

    #pragma unroll
    for (int c = 0; c < NUM_CHUNKS; c++) {
        // Issue next chunk into the other stage (safe: that stage was sealed
        // by the __syncthreads at the end of iteration c-1).
        if (tid == 0 && c + 1 < NUM_CHUNKS) {
            int nstage = (c + 1) & 1;
            int npair = pair0 + (c + 1) * CHUNK_PAIRS;
            uint32_t sa = stage_addr + nstage * STAGE_BYTES;
            asm volatile("mbarrier.arrive.expect_tx.shared.b64 _, [%0], %1;"
                         :: "r"(mb_ck[nstage]), "r"((uint32_t)STAGE_BYTES) : "memory");
            bulk_copy(sa, src + 2 * npair, CHUNK_BYTES, mb_ck[nstage]);
            bulk_copy(sa + CHUNK_BYTES, dst + 2 * npair, CHUNK_BYTES, mb_ck[nstage]);
        }

        if (c == 0) mbar_wait(mb_tab, 0);
        mbar_wait(mb_ck[c & 1], (c >> 1) & 1);

        if (tid < CHUNK_PAIRS) {
            const int2* cs = reinterpret_cast<const int2*>(stage_base + (c & 1) * STAGE_BYTES);
            const int2* cd = reinterpret_cast<const int2*>(stage_base + (c & 1) * STAGE_BYTES + CHUNK_BYTES);
            int2 s2 = cs[tid];
            int2 d2 = cd[tid];
            float2 o;
            o.x = __low2float(s_tab[s2.x]) + __high2float(s_tab[d2.x]);
            o.y = __low2float(s_tab[s2.y]) + __high2float(s_tab[d2.y]);
            __stcs(reinterpret_cast<float2*>(out) + pair0 + c * CHUNK_PAIRS + tid, o);
        }
        __syncthreads();   // seal this stage before it is refilled at c+2
    }
}

extern "C" void kernel_launch(void* const* d_in, const int* in_sizes, int n_in,
                              void* d_out, int out_size) {
    const float* h   = (const float*)d_in[0];
    const int*   src = (const int*)d_in[1];
    const int*   dst = (const int*)d_in[2];
    const float* W   = (const float*)d_in[3];
    const float* b   = (const float*)d_in[4];
    float* out = (float*)d_out;

    // Allow 225.6 KB dynamic smem (idempotent host-side attribute set).
    cudaFuncSetAttribute(gather_kernel,
                         cudaFuncAttributeMaxDynamicSharedMemorySize,
                         SMEM_BYTES);

    // Projection: 6250 warps (8 nodes each), 8 warps per block.
    {
        int blocks = (PROJ_WARPS + PROJ_BLOCK_WARPS - 1) / PROJ_BLOCK_WARPS;
        proj_kernel<<<blocks, PROJ_BLOCK_WARPS * 32>>>(h, W, b);
    }

    // Gather: PDL launch; prologue (mbarrier init + chunk-0 index DMA)
    // overlaps proj's tail.
    {
        cudaLaunchConfig_t cfg = {};
        cfg.gridDim  = dim3(GATHER_BLOCKS, 1, 1);
        cfg.blockDim = dim3(GATHER_THREADS, 1, 1);
        cfg.dynamicSmemBytes = SMEM_BYTES;
        cfg.stream = 0;
        cudaLaunchAttribute attrs[1];
        attrs[0].id = cudaLaunchAttributeProgrammaticStreamSerialization;
        attrs[0].val.programmaticStreamSerializationAllowed = 1;
        cfg.attrs = attrs;
        cfg.numAttrs = 1;
        cudaError_t e = cudaLaunchKernelEx(&cfg, gather_kernel, src, dst, out);
        if (e != cudaSuccess) {
            gather_kernel<<<GATHER_BLOCKS, GATHER_THREADS, SMEM_BYTES>>>(src, dst, out);
        }
    }
}